// round 15
// baseline (speedup 1.0000x reference)
#include <cuda_runtime.h>
#include <cuda_fp16.h>
#include <math.h>
#include <cstdint>

// Problem constants
static constexpr int Bb = 8, Tt = 1024, Cc = 1024, Hh = 16, Dd = 64;
static constexpr int BT = Bb * Tt;      // 8192 rows
static constexpr int C3 = 3 * Cc;       // 3072
static constexpr int FF = 4 * Cc;       // 4096

// Scratch (device globals — no allocation allowed)
__device__ __half g_h[BT * Cc];       // LN output (half, feeds GEMM A)
__device__ __half g_kqv[BT * C3];     // qkv (half — feeds attention)
__device__ __half g_att[BT * Cc];     // attention output (half)
__device__ float  g_x1[BT * Cc];      // x + attn_proj (fp32 residual)
__device__ __half g_mid[BT * FF];     // gelu(fc) (half)
__device__ __half g_wT1[Cc * C3];     // attn_w^T
__device__ __half g_wT2[Cc * Cc];     // attn_proj^T
__device__ __half g_wT3[Cc * FF];     // fc^T
__device__ __half g_wT4[FF * Cc];     // mlp_proj^T

// ---------------------------------------------------------------------------
// Helpers (baseline PTX only — target is sm_103, no 'a' features)
// ---------------------------------------------------------------------------
__device__ __forceinline__ uint32_t smem_u32(const void* p) {
    uint32_t a;
    asm("{ .reg .u64 t; cvta.to.shared.u64 t, %1; cvt.u32.u64 %0, t; }"
        : "=r"(a) : "l"(p));
    return a;
}

__device__ __forceinline__ void cp_async16(uint32_t s, const void* g) {
    asm volatile("cp.async.cg.shared.global [%0], [%1], 16;"
                 :: "r"(s), "l"(g) : "memory");
}
#define CP_COMMIT() asm volatile("cp.async.commit_group;" ::: "memory")
#define CP_WAIT(n)  asm volatile("cp.async.wait_group %0;" :: "n"(n) : "memory")

__device__ __forceinline__ void ldmx4(uint32_t& r0, uint32_t& r1,
                                      uint32_t& r2, uint32_t& r3, uint32_t a) {
    asm volatile("ldmatrix.sync.aligned.m8n8.x4.shared.b16 {%0,%1,%2,%3}, [%4];"
                 : "=r"(r0), "=r"(r1), "=r"(r2), "=r"(r3) : "r"(a));
}

__device__ __forceinline__ void ldmx4t(uint32_t& r0, uint32_t& r1,
                                       uint32_t& r2, uint32_t& r3, uint32_t a) {
    asm volatile("ldmatrix.sync.aligned.m8n8.x4.trans.shared.b16 {%0,%1,%2,%3}, [%4];"
                 : "=r"(r0), "=r"(r1), "=r"(r2), "=r"(r3) : "r"(a));
}

// Scalar-operand mma: NO address-taken temp arrays at the call site.
__device__ __forceinline__ void mma_f16s(float* c,
                                         uint32_t a0, uint32_t a1,
                                         uint32_t a2, uint32_t a3,
                                         uint32_t b0, uint32_t b1) {
    asm volatile(
        "mma.sync.aligned.m16n8k16.row.col.f32.f16.f16.f32 "
        "{%0,%1,%2,%3}, {%4,%5,%6,%7}, {%8,%9}, {%0,%1,%2,%3};"
        : "+f"(c[0]), "+f"(c[1]), "+f"(c[2]), "+f"(c[3])
        : "r"(a0), "r"(a1), "r"(a2), "r"(a3), "r"(b0), "r"(b1));
}

__device__ __forceinline__ float gelu_exact(float x) {
    return 0.5f * x * (1.0f + erff(x * 0.70710678118654752440f));
}

__device__ __forceinline__ uint32_t h2_bits(float a, float b) {
    __half2 h = __floats2half2_rn(a, b);
    return *(uint32_t*)&h;
}

// ---------------------------------------------------------------------------
// LayerNorm: fp32 in, half out (feeds GEMM A operands)
// ---------------------------------------------------------------------------
__global__ __launch_bounds__(256) void ln_kernel(
    const float* __restrict__ x, const float* __restrict__ g,
    const float* __restrict__ b, __half* __restrict__ y)
{
    int row = blockIdx.x;
    const float* xr = x + (size_t)row * Cc;
    __half* yr = y + (size_t)row * Cc;
    int t = threadIdx.x;

    float v[4];
    float s = 0.f, ss = 0.f;
#pragma unroll
    for (int i = 0; i < 4; i++) {
        v[i] = xr[t + i * 256];
        s += v[i];
        ss += v[i] * v[i];
    }
#pragma unroll
    for (int o = 16; o; o >>= 1) {
        s  += __shfl_xor_sync(0xffffffffu, s, o);
        ss += __shfl_xor_sync(0xffffffffu, ss, o);
    }
    __shared__ float red0[8], red1[8];
    int w = t >> 5, lane = t & 31;
    if (lane == 0) { red0[w] = s; red1[w] = ss; }
    __syncthreads();
    if (t < 32) {
        s  = (t < 8) ? red0[t] : 0.f;
        ss = (t < 8) ? red1[t] : 0.f;
#pragma unroll
        for (int o = 4; o; o >>= 1) {
            s  += __shfl_xor_sync(0xffffffffu, s, o);
            ss += __shfl_xor_sync(0xffffffffu, ss, o);
        }
        if (t == 0) { red0[0] = s; red1[0] = ss; }
    }
    __syncthreads();
    float mean = red0[0] * (1.0f / Cc);
    float var  = red1[0] * (1.0f / Cc) - mean * mean;
    float rstd = rsqrtf(var + 1e-5f);
#pragma unroll
    for (int i = 0; i < 4; i++) {
        int c = t + i * 256;
        yr[c] = __float2half_rn((v[i] - mean) * rstd * g[c] + b[c]);
    }
}

// ---------------------------------------------------------------------------
// Weight transpose: in[K][N] fp32 -> out[N][K] half
// ---------------------------------------------------------------------------
__global__ void transpose_kernel(const float* __restrict__ in, __half* __restrict__ out,
                                 int K, int N)
{
    __shared__ float t[32][33];
    int n0 = blockIdx.x * 32, k0 = blockIdx.y * 32;
    int tx = threadIdx.x, ty = threadIdx.y;
#pragma unroll
    for (int i = 0; i < 32; i += 8)
        t[ty + i][tx] = in[(size_t)(k0 + ty + i) * N + n0 + tx];
    __syncthreads();
#pragma unroll
    for (int i = 0; i < 32; i += 8)
        out[(size_t)(n0 + ty + i) * K + k0 + tx] = __float2half_rn(t[tx][ty + i]);
}

// ---------------------------------------------------------------------------
// FP16 mma.sync GEMM (BK=64, validated): Co = A @ Bw^T + bias (+gelu / +res)
// ---------------------------------------------------------------------------
template <int EPI, typename OutT>
__global__ __launch_bounds__(256, 2)
void gemm_h(const __half* __restrict__ A, const __half* __restrict__ Bw,
            const float* __restrict__ bias, const float* __restrict__ res,
            OutT* __restrict__ Co, int M, int N, int K)
{
    extern __shared__ char smem[];
    uint32_t sb = smem_u32(smem);
    int tid = threadIdx.x, wid = tid >> 5, lane = tid & 31;
    int m0 = blockIdx.y * 128, n0 = blockIdx.x * 128;
    int wm = wid >> 2, wn = wid & 3;
    int g = lane >> 2, tig = lane & 3;

    const int NCH = K >> 6;
    constexpr int STG = 32768;

    auto load_stage = [&](int s, int kc) {
        int k0 = kc << 6;
        uint32_t base = sb + s * STG;
#pragma unroll
        for (int i = 0; i < 4; i++) {
            int idx = tid + i * 256;
            int r = idx >> 3, q = idx & 7;
            uint32_t sw = (uint32_t)(r * 128 + ((q ^ (r & 7)) << 4));
            cp_async16(base + sw,         A  + (size_t)(m0 + r) * K + k0 + q * 8);
            cp_async16(base + 16384 + sw, Bw + (size_t)(n0 + r) * K + k0 + q * 8);
        }
    };

    float acc[4][4][4];
#pragma unroll
    for (int i = 0; i < 4; i++)
#pragma unroll
        for (int j = 0; j < 4; j++)
#pragma unroll
            for (int k = 0; k < 4; k++) acc[i][j][k] = 0.f;

    load_stage(0, 0); CP_COMMIT();
    load_stage(1, 1); CP_COMMIT();

    int a_r = lane & 15;
    int a_q = lane >> 4;
    int b_r = (((lane >> 3) & 1) << 3) + (lane & 7);
    int b_q = lane >> 4;

    for (int ki = 0; ki < NCH; ki++) {
        int s = ki % 3;
        CP_WAIT(1);
        __syncthreads();

        uint32_t abase = sb + s * STG;
        uint32_t bbase = abase + 16384;

#pragma unroll
        for (int ks = 0; ks < 4; ks++) {
            uint32_t af[4][4], bf[2][4];
#pragma unroll
            for (int mt = 0; mt < 4; mt++) {
                int r = wm * 64 + mt * 16 + a_r;
                int q = ks * 2 + a_q;
                uint32_t ad = abase + (uint32_t)(r * 128 + ((q ^ (r & 7)) << 4));
                ldmx4(af[mt][0], af[mt][1], af[mt][2], af[mt][3], ad);
            }
#pragma unroll
            for (int np = 0; np < 2; np++) {
                int r = wn * 32 + np * 16 + b_r;
                int q = ks * 2 + b_q;
                uint32_t bd = bbase + (uint32_t)(r * 128 + ((q ^ (r & 7)) << 4));
                ldmx4(bf[np][0], bf[np][1], bf[np][2], bf[np][3], bd);
            }
#pragma unroll
            for (int mt = 0; mt < 4; mt++) {
#pragma unroll
                for (int nt = 0; nt < 4; nt++) {
                    mma_f16s(acc[mt][nt],
                             af[mt][0], af[mt][1], af[mt][2], af[mt][3],
                             bf[nt >> 1][(nt & 1)], bf[nt >> 1][(nt & 1) + 2]);
                }
            }
        }

        int kn = ki + 2;
        if (kn < NCH) load_stage(kn % 3, kn);
        CP_COMMIT();
    }

#pragma unroll
    for (int mt = 0; mt < 4; mt++) {
#pragma unroll
        for (int nt = 0; nt < 4; nt++) {
            int row = m0 + wm * 64 + mt * 16 + g;
            int col = n0 + wn * 32 + nt * 8 + 2 * tig;
            float b0 = bias[col], b1 = bias[col + 1];
#pragma unroll
            for (int h = 0; h < 2; h++) {
                int r = row + h * 8;
                size_t go = (size_t)r * N + col;
                float v0 = acc[mt][nt][2 * h + 0] + b0;
                float v1 = acc[mt][nt][2 * h + 1] + b1;
                if (EPI == 1) {
                    v0 = gelu_exact(v0);
                    v1 = gelu_exact(v1);
                }
                if (EPI == 2) {
                    float2 rr = *(const float2*)&res[go];
                    v0 += rr.x; v1 += rr.y;
                }
                if constexpr (sizeof(OutT) == 2) {
                    *(__half2*)&Co[go] = __floats2half2_rn(v0, v1);
                } else {
                    float2 o; o.x = v0; o.y = v1;
                    *(float2*)&Co[go] = o;
                }
            }
        }
    }
}

// ---------------------------------------------------------------------------
// FP16 tensor-core causal flash attention, v2:
//  - P stays in registers: S-mma C-fragment layout == P@V A-fragment layout
//    (c0,c1=(g,nt*8+2tig..+1), c2,c3=(g+8,..) -> a0..a3 of k-step nt/2),
//    so exp() results pack straight into pa[][]. No P smem, no extra syncwarp.
//  - Reversed i-tile rasterization: long blocks (it=15) launch first.
// Reference quirk: kqv splits k,q,v (k FIRST); wei[i,j] = k_i . q_j.
// ---------------------------------------------------------------------------
static constexpr int AKB = 0;          // K tile: 8192 B
static constexpr int AQB = 8192;       // Q stages: + s*8192
static constexpr int AVB = 24576;      // V stages: + s*8192
static constexpr int ATT_SMEM = 40960;

__global__ __launch_bounds__(128, 2)
void attn_h(const __half* __restrict__ kqv, __half* __restrict__ out)
{
    extern __shared__ char smc[];
    uint32_t sb = smem_u32(smc);

    int it = (int)gridDim.x - 1 - (int)blockIdx.x;   // long blocks first
    int bh = blockIdx.y;
    int b = bh >> 4, h = bh & 15;
    int tid = threadIdx.x, wid = tid >> 5, lane = tid & 31;
    int g = lane >> 2, tig = lane & 3;
    int i0 = it * 64;

    const __half* kp = kqv + (size_t)b * Tt * C3 + h * Dd;
    const __half* qp = kp + Cc;
    const __half* vp = kp + 2 * Cc;

    auto ldqv = [&](int jt, int s) {
        int j0 = jt * 64;
#pragma unroll
        for (int i = tid; i < 512; i += 128) {
            int r = i >> 3, q = i & 7;
            uint32_t sw = (uint32_t)(r * 128 + ((q ^ (r & 7)) << 4));
            cp_async16(sb + AQB + s * 8192 + sw, qp + (size_t)(j0 + r) * C3 + q * 8);
            cp_async16(sb + AVB + s * 8192 + sw, vp + (size_t)(j0 + r) * C3 + q * 8);
        }
    };

#pragma unroll
    for (int i = tid; i < 512; i += 128) {
        int r = i >> 3, q = i & 7;
        uint32_t sw = (uint32_t)(r * 128 + ((q ^ (r & 7)) << 4));
        cp_async16(sb + AKB + sw, kp + (size_t)(i0 + r) * C3 + q * 8);
    }
    CP_COMMIT();
    ldqv(0, 0);
    CP_COMMIT();

    CP_WAIT(1);
    __syncthreads();

    int a_r = lane & 15, a_q = lane >> 4;
    int b_r = (((lane >> 3) & 1) << 3) + (lane & 7);
    int b_q = lane >> 4;

    // K A-fragments (k16 steps: 4 over D=64)
    uint32_t af[4][4];
#pragma unroll
    for (int kd = 0; kd < 4; kd++) {
        int r = wid * 16 + a_r;
        int q = kd * 2 + a_q;
        ldmx4(af[kd][0], af[kd][1], af[kd][2], af[kd][3],
              sb + AKB + (uint32_t)(r * 128 + ((q ^ (r & 7)) << 4)));
    }

    float oacc[8][4];
#pragma unroll
    for (int nt = 0; nt < 8; nt++)
#pragma unroll
        for (int c = 0; c < 4; c++) oacc[nt][c] = 0.f;
    float m0v = -1e30f, m1v = -1e30f, l0 = 0.f, l1 = 0.f;

    int mr0 = wid * 16 + g;
    int grow0 = i0 + mr0;
    int grow1 = grow0 + 8;

    for (int jt = 0; jt <= it; jt++) {
        int cur = jt & 1;
        if (jt < it) { ldqv(jt + 1, cur ^ 1); CP_COMMIT(); CP_WAIT(1); }
        else         { CP_WAIT(0); }
        __syncthreads();

        uint32_t qb = sb + AQB + cur * 8192;
        uint32_t vb = sb + AVB + cur * 8192;

        // S = K @ Q^T
        float sacc[8][4];
#pragma unroll
        for (int nt = 0; nt < 8; nt++)
#pragma unroll
            for (int c = 0; c < 4; c++) sacc[nt][c] = 0.f;

#pragma unroll
        for (int kd = 0; kd < 4; kd++) {
#pragma unroll
            for (int nh = 0; nh < 4; nh++) {
                int r = nh * 16 + b_r;
                int q = kd * 2 + b_q;
                uint32_t f0, f1, f2, f3;
                ldmx4(f0, f1, f2, f3,
                      qb + (uint32_t)(r * 128 + ((q ^ (r & 7)) << 4)));
                mma_f16s(sacc[nh * 2 + 0], af[kd][0], af[kd][1], af[kd][2], af[kd][3], f0, f2);
                mma_f16s(sacc[nh * 2 + 1], af[kd][0], af[kd][1], af[kd][2], af[kd][3], f1, f3);
            }
        }

        // scale + causal mask + row max
        bool diag = (jt == it);
        float rmax0 = -1e30f, rmax1 = -1e30f;
#pragma unroll
        for (int nt = 0; nt < 8; nt++) {
            int jc0 = jt * 64 + nt * 8 + 2 * tig;
#pragma unroll
            for (int c = 0; c < 4; c++) {
                int j = jc0 + (c & 1);
                float v = sacc[nt][c] * 0.125f;
                if (diag && j > ((c < 2) ? grow0 : grow1)) v = -1e30f;
                sacc[nt][c] = v;
                if (c < 2) rmax0 = fmaxf(rmax0, v);
                else       rmax1 = fmaxf(rmax1, v);
            }
        }
#pragma unroll
        for (int o = 1; o <= 2; o <<= 1) {
            rmax0 = fmaxf(rmax0, __shfl_xor_sync(0xffffffffu, rmax0, o));
            rmax1 = fmaxf(rmax1, __shfl_xor_sync(0xffffffffu, rmax1, o));
        }
        float mn0 = fmaxf(m0v, rmax0), mn1 = fmaxf(m1v, rmax1);
        float corr0 = __expf(m0v - mn0), corr1 = __expf(m1v - mn1);
        m0v = mn0; m1v = mn1;

        // exp -> P fragments directly in registers (C-frag == A-frag layout)
        uint32_t pa[4][4];
        float rs0 = 0.f, rs1 = 0.f;
#pragma unroll
        for (int nt = 0; nt < 8; nt++) {
            float p0 = __expf(sacc[nt][0] - mn0);
            float p1 = __expf(sacc[nt][1] - mn0);
            float p2 = __expf(sacc[nt][2] - mn1);
            float p3 = __expf(sacc[nt][3] - mn1);
            rs0 += p0 + p1;
            rs1 += p2 + p3;
            pa[nt >> 1][(nt & 1) * 2 + 0] = h2_bits(p0, p1);  // rows g
            pa[nt >> 1][(nt & 1) * 2 + 1] = h2_bits(p2, p3);  // rows g+8
        }
#pragma unroll
        for (int o = 1; o <= 2; o <<= 1) {
            rs0 += __shfl_xor_sync(0xffffffffu, rs0, o);
            rs1 += __shfl_xor_sync(0xffffffffu, rs1, o);
        }
        l0 = l0 * corr0 + rs0;
        l1 = l1 * corr1 + rs1;

        // rescale O
#pragma unroll
        for (int nt = 0; nt < 8; nt++) {
            oacc[nt][0] *= corr0; oacc[nt][1] *= corr0;
            oacc[nt][2] *= corr1; oacc[nt][3] *= corr1;
        }

        // O += P @ V   (P from registers; V via ldmatrix.trans as B)
#pragma unroll
        for (int kd = 0; kd < 4; kd++) {
#pragma unroll
            for (int nh = 0; nh < 4; nh++) {
                int r = kd * 16 + b_r;
                int q = nh * 2 + b_q;
                uint32_t f0, f1, f2, f3;
                ldmx4t(f0, f1, f2, f3,
                       vb + (uint32_t)(r * 128 + ((q ^ (r & 7)) << 4)));
                mma_f16s(oacc[nh * 2 + 0], pa[kd][0], pa[kd][1], pa[kd][2], pa[kd][3], f0, f1);
                mma_f16s(oacc[nh * 2 + 1], pa[kd][0], pa[kd][1], pa[kd][2], pa[kd][3], f2, f3);
            }
        }
        __syncthreads();   // protect Q/V stage `cur` before next overwrite
    }

    float inv0 = 1.0f / l0, inv1 = 1.0f / l1;
    size_t ro0 = (size_t)(b * Tt + grow0) * Cc + h * Dd;
    size_t ro1 = (size_t)(b * Tt + grow1) * Cc + h * Dd;
#pragma unroll
    for (int nt = 0; nt < 8; nt++) {
        int col = nt * 8 + 2 * tig;
        *(__half2*)&out[ro0 + col] =
            __floats2half2_rn(oacc[nt][0] * inv0, oacc[nt][1] * inv0);
        *(__half2*)&out[ro1 + col] =
            __floats2half2_rn(oacc[nt][2] * inv1, oacc[nt][3] * inv1);
    }
}

// ---------------------------------------------------------------------------
// Launch
// ---------------------------------------------------------------------------
static constexpr int GEMM_SMEM = 3 * 32768;  // 98304 bytes

extern "C" void kernel_launch(void* const* d_in, const int* in_sizes, int n_in,
                              void* d_out, int out_size)
{
    const float* x           = (const float*)d_in[0];
    const float* ln1_g       = (const float*)d_in[1];
    const float* ln1_b       = (const float*)d_in[2];
    const float* attn_w      = (const float*)d_in[3];
    const float* attn_b      = (const float*)d_in[4];
    const float* attn_proj_w = (const float*)d_in[5];
    const float* attn_proj_b = (const float*)d_in[6];
    const float* ln2_g       = (const float*)d_in[7];
    const float* ln2_b       = (const float*)d_in[8];
    const float* fc_w        = (const float*)d_in[9];
    const float* fc_b        = (const float*)d_in[10];
    const float* mlp_proj_w  = (const float*)d_in[11];
    const float* mlp_proj_b  = (const float*)d_in[12];
    float* out = (float*)d_out;

    __half *h, *kqvb, *att, *mid, *wT1, *wT2, *wT3, *wT4;
    float *x1;
    cudaGetSymbolAddress((void**)&h,    g_h);
    cudaGetSymbolAddress((void**)&kqvb, g_kqv);
    cudaGetSymbolAddress((void**)&att,  g_att);
    cudaGetSymbolAddress((void**)&x1,   g_x1);
    cudaGetSymbolAddress((void**)&mid,  g_mid);
    cudaGetSymbolAddress((void**)&wT1,  g_wT1);
    cudaGetSymbolAddress((void**)&wT2,  g_wT2);
    cudaGetSymbolAddress((void**)&wT3,  g_wT3);
    cudaGetSymbolAddress((void**)&wT4,  g_wT4);

    static bool attr_set = false;
    if (!attr_set) {
        cudaFuncSetAttribute((const void*)gemm_h<0, __half>, cudaFuncAttributeMaxDynamicSharedMemorySize, GEMM_SMEM);
        cudaFuncSetAttribute((const void*)gemm_h<1, __half>, cudaFuncAttributeMaxDynamicSharedMemorySize, GEMM_SMEM);
        cudaFuncSetAttribute((const void*)gemm_h<2, float>,  cudaFuncAttributeMaxDynamicSharedMemorySize, GEMM_SMEM);
        cudaFuncSetAttribute((const void*)attn_h, cudaFuncAttributeMaxDynamicSharedMemorySize, ATT_SMEM);
        attr_set = true;
    }

    // weight transposes: [K,N] fp32 -> [N,K] half
    transpose_kernel<<<dim3(C3 / 32, Cc / 32), dim3(32, 8)>>>(attn_w,      wT1, Cc, C3);
    transpose_kernel<<<dim3(Cc / 32, Cc / 32), dim3(32, 8)>>>(attn_proj_w, wT2, Cc, Cc);
    transpose_kernel<<<dim3(FF / 32, Cc / 32), dim3(32, 8)>>>(fc_w,        wT3, Cc, FF);
    transpose_kernel<<<dim3(Cc / 32, FF / 32), dim3(32, 8)>>>(mlp_proj_w,  wT4, FF, Cc);

    // 1. h = LN1(x)
    ln_kernel<<<BT, 256>>>(x, ln1_g, ln1_b, h);
    // 2. kqv = h @ attn_w + attn_b   (half out — feeds attention)
    gemm_h<0, __half><<<dim3(C3 / 128, BT / 128), 256, GEMM_SMEM>>>(h, wT1, attn_b, nullptr, kqvb, BT, C3, Cc);
    // 3. causal attention (fp16 tensor cores)
    attn_h<<<dim3(Tt / 64, Bb * Hh), 128, ATT_SMEM>>>(kqvb, att);
    // 4. x1 = x + att @ attn_proj_w + attn_proj_b
    gemm_h<2, float><<<dim3(Cc / 128, BT / 128), 256, GEMM_SMEM>>>(att, wT2, attn_proj_b, x, x1, BT, Cc, Cc);
    // 5. h = LN2(x1)
    ln_kernel<<<BT, 256>>>(x1, ln2_g, ln2_b, h);
    // 6. mid = gelu(h @ fc_w + fc_b)  (half out)
    gemm_h<1, __half><<<dim3(FF / 128, BT / 128), 256, GEMM_SMEM>>>(h, wT3, fc_b, nullptr, mid, BT, FF, Cc);
    // 7. out = x1 + mid @ mlp_proj_w + mlp_proj_b
    gemm_h<2, float><<<dim3(Cc / 128, BT / 128), 256, GEMM_SMEM>>>(mid, wT4, mlp_proj_b, x1, out, BT, Cc, FF);
}

// round 16
// speedup vs baseline: 1.5293x; 1.5293x over previous
#include <cuda_runtime.h>
#include <cuda_fp16.h>
#include <math.h>
#include <cstdint>

// Problem constants
static constexpr int Bb = 8, Tt = 1024, Cc = 1024, Hh = 16, Dd = 64;
static constexpr int BT = Bb * Tt;      // 8192 rows
static constexpr int C3 = 3 * Cc;       // 3072
static constexpr int FF = 4 * Cc;       // 4096

// Scratch (device globals — no allocation allowed)
__device__ __half g_h[BT * Cc];       // LN output (half, feeds GEMM A)
__device__ __half g_kqv[BT * C3];     // qkv (half — feeds attention)
__device__ __half g_att[BT * Cc];     // attention output (half)
__device__ float  g_x1[BT * Cc];      // x + attn_proj (fp32 residual)
__device__ __half g_mid[BT * FF];     // gelu(fc) (half)
__device__ __half g_wT1[Cc * C3];     // attn_w^T
__device__ __half g_wT2[Cc * Cc];     // attn_proj^T
__device__ __half g_wT3[Cc * FF];     // fc^T
__device__ __half g_wT4[FF * Cc];     // mlp_proj^T

// ---------------------------------------------------------------------------
// Helpers (baseline PTX only — target is sm_103, no 'a' features)
// ---------------------------------------------------------------------------
__device__ __forceinline__ uint32_t smem_u32(const void* p) {
    uint32_t a;
    asm("{ .reg .u64 t; cvta.to.shared.u64 t, %1; cvt.u32.u64 %0, t; }"
        : "=r"(a) : "l"(p));
    return a;
}

__device__ __forceinline__ void cp_async16(uint32_t s, const void* g) {
    asm volatile("cp.async.cg.shared.global [%0], [%1], 16;"
                 :: "r"(s), "l"(g) : "memory");
}
#define CP_COMMIT() asm volatile("cp.async.commit_group;" ::: "memory")
#define CP_WAIT(n)  asm volatile("cp.async.wait_group %0;" :: "n"(n) : "memory")

__device__ __forceinline__ void ldmx4(uint32_t& r0, uint32_t& r1,
                                      uint32_t& r2, uint32_t& r3, uint32_t a) {
    asm volatile("ldmatrix.sync.aligned.m8n8.x4.shared.b16 {%0,%1,%2,%3}, [%4];"
                 : "=r"(r0), "=r"(r1), "=r"(r2), "=r"(r3) : "r"(a));
}

__device__ __forceinline__ void ldmx4t(uint32_t& r0, uint32_t& r1,
                                       uint32_t& r2, uint32_t& r3, uint32_t a) {
    asm volatile("ldmatrix.sync.aligned.m8n8.x4.trans.shared.b16 {%0,%1,%2,%3}, [%4];"
                 : "=r"(r0), "=r"(r1), "=r"(r2), "=r"(r3) : "r"(a));
}

// Scalar-operand mma: NO address-taken temp arrays at the call site.
__device__ __forceinline__ void mma_f16s(float* c,
                                         uint32_t a0, uint32_t a1,
                                         uint32_t a2, uint32_t a3,
                                         uint32_t b0, uint32_t b1) {
    asm volatile(
        "mma.sync.aligned.m16n8k16.row.col.f32.f16.f16.f32 "
        "{%0,%1,%2,%3}, {%4,%5,%6,%7}, {%8,%9}, {%0,%1,%2,%3};"
        : "+f"(c[0]), "+f"(c[1]), "+f"(c[2]), "+f"(c[3])
        : "r"(a0), "r"(a1), "r"(a2), "r"(a3), "r"(b0), "r"(b1));
}

__device__ __forceinline__ float gelu_exact(float x) {
    return 0.5f * x * (1.0f + erff(x * 0.70710678118654752440f));
}

// Register-only f32x2 -> f16x2 pack (NO address-taken locals).
// PTX cvt packs FIRST source into the HIGH half, SECOND into the LOW half.
__device__ __forceinline__ uint32_t h2_bits(float lo, float hi) {
    uint32_t r;
    asm("cvt.rn.f16x2.f32 %0, %1, %2;" : "=r"(r) : "f"(hi), "f"(lo));
    return r;
}

// ---------------------------------------------------------------------------
// LayerNorm: fp32 in, half out (feeds GEMM A operands)
// ---------------------------------------------------------------------------
__global__ __launch_bounds__(256) void ln_kernel(
    const float* __restrict__ x, const float* __restrict__ g,
    const float* __restrict__ b, __half* __restrict__ y)
{
    int row = blockIdx.x;
    const float* xr = x + (size_t)row * Cc;
    __half* yr = y + (size_t)row * Cc;
    int t = threadIdx.x;

    float v[4];
    float s = 0.f, ss = 0.f;
#pragma unroll
    for (int i = 0; i < 4; i++) {
        v[i] = xr[t + i * 256];
        s += v[i];
        ss += v[i] * v[i];
    }
#pragma unroll
    for (int o = 16; o; o >>= 1) {
        s  += __shfl_xor_sync(0xffffffffu, s, o);
        ss += __shfl_xor_sync(0xffffffffu, ss, o);
    }
    __shared__ float red0[8], red1[8];
    int w = t >> 5, lane = t & 31;
    if (lane == 0) { red0[w] = s; red1[w] = ss; }
    __syncthreads();
    if (t < 32) {
        s  = (t < 8) ? red0[t] : 0.f;
        ss = (t < 8) ? red1[t] : 0.f;
#pragma unroll
        for (int o = 4; o; o >>= 1) {
            s  += __shfl_xor_sync(0xffffffffu, s, o);
            ss += __shfl_xor_sync(0xffffffffu, ss, o);
        }
        if (t == 0) { red0[0] = s; red1[0] = ss; }
    }
    __syncthreads();
    float mean = red0[0] * (1.0f / Cc);
    float var  = red1[0] * (1.0f / Cc) - mean * mean;
    float rstd = rsqrtf(var + 1e-5f);
#pragma unroll
    for (int i = 0; i < 4; i++) {
        int c = t + i * 256;
        yr[c] = __float2half_rn((v[i] - mean) * rstd * g[c] + b[c]);
    }
}

// ---------------------------------------------------------------------------
// Weight transpose: in[K][N] fp32 -> out[N][K] half
// ---------------------------------------------------------------------------
__global__ void transpose_kernel(const float* __restrict__ in, __half* __restrict__ out,
                                 int K, int N)
{
    __shared__ float t[32][33];
    int n0 = blockIdx.x * 32, k0 = blockIdx.y * 32;
    int tx = threadIdx.x, ty = threadIdx.y;
#pragma unroll
    for (int i = 0; i < 32; i += 8)
        t[ty + i][tx] = in[(size_t)(k0 + ty + i) * N + n0 + tx];
    __syncthreads();
#pragma unroll
    for (int i = 0; i < 32; i += 8)
        out[(size_t)(n0 + ty + i) * K + k0 + tx] = __float2half_rn(t[tx][ty + i]);
}

// ---------------------------------------------------------------------------
// FP16 mma.sync GEMM (BK=64, validated): Co = A @ Bw^T + bias (+gelu / +res)
// ---------------------------------------------------------------------------
template <int EPI, typename OutT>
__global__ __launch_bounds__(256, 2)
void gemm_h(const __half* __restrict__ A, const __half* __restrict__ Bw,
            const float* __restrict__ bias, const float* __restrict__ res,
            OutT* __restrict__ Co, int M, int N, int K)
{
    extern __shared__ char smem[];
    uint32_t sb = smem_u32(smem);
    int tid = threadIdx.x, wid = tid >> 5, lane = tid & 31;
    int m0 = blockIdx.y * 128, n0 = blockIdx.x * 128;
    int wm = wid >> 2, wn = wid & 3;
    int g = lane >> 2, tig = lane & 3;

    const int NCH = K >> 6;
    constexpr int STG = 32768;

    auto load_stage = [&](int s, int kc) {
        int k0 = kc << 6;
        uint32_t base = sb + s * STG;
#pragma unroll
        for (int i = 0; i < 4; i++) {
            int idx = tid + i * 256;
            int r = idx >> 3, q = idx & 7;
            uint32_t sw = (uint32_t)(r * 128 + ((q ^ (r & 7)) << 4));
            cp_async16(base + sw,         A  + (size_t)(m0 + r) * K + k0 + q * 8);
            cp_async16(base + 16384 + sw, Bw + (size_t)(n0 + r) * K + k0 + q * 8);
        }
    };

    float acc[4][4][4];
#pragma unroll
    for (int i = 0; i < 4; i++)
#pragma unroll
        for (int j = 0; j < 4; j++)
#pragma unroll
            for (int k = 0; k < 4; k++) acc[i][j][k] = 0.f;

    load_stage(0, 0); CP_COMMIT();
    load_stage(1, 1); CP_COMMIT();

    int a_r = lane & 15;
    int a_q = lane >> 4;
    int b_r = (((lane >> 3) & 1) << 3) + (lane & 7);
    int b_q = lane >> 4;

    for (int ki = 0; ki < NCH; ki++) {
        int s = ki % 3;
        CP_WAIT(1);
        __syncthreads();

        uint32_t abase = sb + s * STG;
        uint32_t bbase = abase + 16384;

#pragma unroll
        for (int ks = 0; ks < 4; ks++) {
            uint32_t af[4][4], bf[2][4];
#pragma unroll
            for (int mt = 0; mt < 4; mt++) {
                int r = wm * 64 + mt * 16 + a_r;
                int q = ks * 2 + a_q;
                uint32_t ad = abase + (uint32_t)(r * 128 + ((q ^ (r & 7)) << 4));
                ldmx4(af[mt][0], af[mt][1], af[mt][2], af[mt][3], ad);
            }
#pragma unroll
            for (int np = 0; np < 2; np++) {
                int r = wn * 32 + np * 16 + b_r;
                int q = ks * 2 + b_q;
                uint32_t bd = bbase + (uint32_t)(r * 128 + ((q ^ (r & 7)) << 4));
                ldmx4(bf[np][0], bf[np][1], bf[np][2], bf[np][3], bd);
            }
#pragma unroll
            for (int mt = 0; mt < 4; mt++) {
#pragma unroll
                for (int nt = 0; nt < 4; nt++) {
                    mma_f16s(acc[mt][nt],
                             af[mt][0], af[mt][1], af[mt][2], af[mt][3],
                             bf[nt >> 1][(nt & 1)], bf[nt >> 1][(nt & 1) + 2]);
                }
            }
        }

        int kn = ki + 2;
        if (kn < NCH) load_stage(kn % 3, kn);
        CP_COMMIT();
    }

#pragma unroll
    for (int mt = 0; mt < 4; mt++) {
#pragma unroll
        for (int nt = 0; nt < 4; nt++) {
            int row = m0 + wm * 64 + mt * 16 + g;
            int col = n0 + wn * 32 + nt * 8 + 2 * tig;
            float b0 = bias[col], b1 = bias[col + 1];
#pragma unroll
            for (int h = 0; h < 2; h++) {
                int r = row + h * 8;
                size_t go = (size_t)r * N + col;
                float v0 = acc[mt][nt][2 * h + 0] + b0;
                float v1 = acc[mt][nt][2 * h + 1] + b1;
                if (EPI == 1) {
                    v0 = gelu_exact(v0);
                    v1 = gelu_exact(v1);
                }
                if (EPI == 2) {
                    float2 rr = *(const float2*)&res[go];
                    v0 += rr.x; v1 += rr.y;
                }
                if constexpr (sizeof(OutT) == 2) {
                    *(__half2*)&Co[go] = __floats2half2_rn(v0, v1);
                } else {
                    float2 o; o.x = v0; o.y = v1;
                    *(float2*)&Co[go] = o;
                }
            }
        }
    }
}

// ---------------------------------------------------------------------------
// FP16 tensor-core causal flash attention, v2 re-land with spill-free pack:
//  - P stays in registers (S C-frag layout == P@V A-frag layout); exp()
//    results packed via register-only cvt.rn.f16x2.f32 (NO address-taken
//    locals — the R14 h2_bits reinterpret was the regression).
//  - Reversed i-tile rasterization: long blocks (it=15) launch first.
// Reference quirk: kqv splits k,q,v (k FIRST); wei[i,j] = k_i . q_j.
// ---------------------------------------------------------------------------
static constexpr int AKB = 0;          // K tile: 8192 B
static constexpr int AQB = 8192;       // Q stages: + s*8192
static constexpr int AVB = 24576;      // V stages: + s*8192
static constexpr int ATT_SMEM = 40960;

__global__ __launch_bounds__(128, 2)
void attn_h(const __half* __restrict__ kqv, __half* __restrict__ out)
{
    extern __shared__ char smc[];
    uint32_t sb = smem_u32(smc);

    int it = (int)gridDim.x - 1 - (int)blockIdx.x;   // long blocks first
    int bh = blockIdx.y;
    int b = bh >> 4, h = bh & 15;
    int tid = threadIdx.x, wid = tid >> 5, lane = tid & 31;
    int g = lane >> 2, tig = lane & 3;
    int i0 = it * 64;

    const __half* kp = kqv + (size_t)b * Tt * C3 + h * Dd;
    const __half* qp = kp + Cc;
    const __half* vp = kp + 2 * Cc;

    auto ldqv = [&](int jt, int s) {
        int j0 = jt * 64;
#pragma unroll
        for (int i = tid; i < 512; i += 128) {
            int r = i >> 3, q = i & 7;
            uint32_t sw = (uint32_t)(r * 128 + ((q ^ (r & 7)) << 4));
            cp_async16(sb + AQB + s * 8192 + sw, qp + (size_t)(j0 + r) * C3 + q * 8);
            cp_async16(sb + AVB + s * 8192 + sw, vp + (size_t)(j0 + r) * C3 + q * 8);
        }
    };

#pragma unroll
    for (int i = tid; i < 512; i += 128) {
        int r = i >> 3, q = i & 7;
        uint32_t sw = (uint32_t)(r * 128 + ((q ^ (r & 7)) << 4));
        cp_async16(sb + AKB + sw, kp + (size_t)(i0 + r) * C3 + q * 8);
    }
    CP_COMMIT();
    ldqv(0, 0);
    CP_COMMIT();

    CP_WAIT(1);
    __syncthreads();

    int a_r = lane & 15, a_q = lane >> 4;
    int b_r = (((lane >> 3) & 1) << 3) + (lane & 7);
    int b_q = lane >> 4;

    // K A-fragments (k16 steps: 4 over D=64)
    uint32_t af[4][4];
#pragma unroll
    for (int kd = 0; kd < 4; kd++) {
        int r = wid * 16 + a_r;
        int q = kd * 2 + a_q;
        ldmx4(af[kd][0], af[kd][1], af[kd][2], af[kd][3],
              sb + AKB + (uint32_t)(r * 128 + ((q ^ (r & 7)) << 4)));
    }

    float oacc[8][4];
#pragma unroll
    for (int nt = 0; nt < 8; nt++)
#pragma unroll
        for (int c = 0; c < 4; c++) oacc[nt][c] = 0.f;
    float m0v = -1e30f, m1v = -1e30f, l0 = 0.f, l1 = 0.f;

    int mr0 = wid * 16 + g;
    int grow0 = i0 + mr0;
    int grow1 = grow0 + 8;

    for (int jt = 0; jt <= it; jt++) {
        int cur = jt & 1;
        if (jt < it) { ldqv(jt + 1, cur ^ 1); CP_COMMIT(); CP_WAIT(1); }
        else         { CP_WAIT(0); }
        __syncthreads();

        uint32_t qb = sb + AQB + cur * 8192;
        uint32_t vb = sb + AVB + cur * 8192;

        // S = K @ Q^T
        float sacc[8][4];
#pragma unroll
        for (int nt = 0; nt < 8; nt++)
#pragma unroll
            for (int c = 0; c < 4; c++) sacc[nt][c] = 0.f;

#pragma unroll
        for (int kd = 0; kd < 4; kd++) {
#pragma unroll
            for (int nh = 0; nh < 4; nh++) {
                int r = nh * 16 + b_r;
                int q = kd * 2 + b_q;
                uint32_t f0, f1, f2, f3;
                ldmx4(f0, f1, f2, f3,
                      qb + (uint32_t)(r * 128 + ((q ^ (r & 7)) << 4)));
                mma_f16s(sacc[nh * 2 + 0], af[kd][0], af[kd][1], af[kd][2], af[kd][3], f0, f2);
                mma_f16s(sacc[nh * 2 + 1], af[kd][0], af[kd][1], af[kd][2], af[kd][3], f1, f3);
            }
        }

        // scale + causal mask + row max
        bool diag = (jt == it);
        float rmax0 = -1e30f, rmax1 = -1e30f;
#pragma unroll
        for (int nt = 0; nt < 8; nt++) {
            int jc0 = jt * 64 + nt * 8 + 2 * tig;
#pragma unroll
            for (int c = 0; c < 4; c++) {
                int j = jc0 + (c & 1);
                float v = sacc[nt][c] * 0.125f;
                if (diag && j > ((c < 2) ? grow0 : grow1)) v = -1e30f;
                sacc[nt][c] = v;
                if (c < 2) rmax0 = fmaxf(rmax0, v);
                else       rmax1 = fmaxf(rmax1, v);
            }
        }
#pragma unroll
        for (int o = 1; o <= 2; o <<= 1) {
            rmax0 = fmaxf(rmax0, __shfl_xor_sync(0xffffffffu, rmax0, o));
            rmax1 = fmaxf(rmax1, __shfl_xor_sync(0xffffffffu, rmax1, o));
        }
        float mn0 = fmaxf(m0v, rmax0), mn1 = fmaxf(m1v, rmax1);
        float corr0 = __expf(m0v - mn0), corr1 = __expf(m1v - mn1);
        m0v = mn0; m1v = mn1;

        // exp -> P fragments directly in registers (C-frag == A-frag layout)
        uint32_t pa[4][4];
        float rs0 = 0.f, rs1 = 0.f;
#pragma unroll
        for (int nt = 0; nt < 8; nt++) {
            float p0 = __expf(sacc[nt][0] - mn0);
            float p1 = __expf(sacc[nt][1] - mn0);
            float p2 = __expf(sacc[nt][2] - mn1);
            float p3 = __expf(sacc[nt][3] - mn1);
            rs0 += p0 + p1;
            rs1 += p2 + p3;
            pa[nt >> 1][(nt & 1) * 2 + 0] = h2_bits(p0, p1);  // rows g
            pa[nt >> 1][(nt & 1) * 2 + 1] = h2_bits(p2, p3);  // rows g+8
        }
#pragma unroll
        for (int o = 1; o <= 2; o <<= 1) {
            rs0 += __shfl_xor_sync(0xffffffffu, rs0, o);
            rs1 += __shfl_xor_sync(0xffffffffu, rs1, o);
        }
        l0 = l0 * corr0 + rs0;
        l1 = l1 * corr1 + rs1;

        // rescale O
#pragma unroll
        for (int nt = 0; nt < 8; nt++) {
            oacc[nt][0] *= corr0; oacc[nt][1] *= corr0;
            oacc[nt][2] *= corr1; oacc[nt][3] *= corr1;
        }

        // O += P @ V   (P from registers; V via ldmatrix.trans as B)
#pragma unroll
        for (int kd = 0; kd < 4; kd++) {
#pragma unroll
            for (int nh = 0; nh < 4; nh++) {
                int r = kd * 16 + b_r;
                int q = nh * 2 + b_q;
                uint32_t f0, f1, f2, f3;
                ldmx4t(f0, f1, f2, f3,
                       vb + (uint32_t)(r * 128 + ((q ^ (r & 7)) << 4)));
                mma_f16s(oacc[nh * 2 + 0], pa[kd][0], pa[kd][1], pa[kd][2], pa[kd][3], f0, f1);
                mma_f16s(oacc[nh * 2 + 1], pa[kd][0], pa[kd][1], pa[kd][2], pa[kd][3], f2, f3);
            }
        }
        __syncthreads();   // protect Q/V stage `cur` before next overwrite
    }

    float inv0 = 1.0f / l0, inv1 = 1.0f / l1;
    size_t ro0 = (size_t)(b * Tt + grow0) * Cc + h * Dd;
    size_t ro1 = (size_t)(b * Tt + grow1) * Cc + h * Dd;
#pragma unroll
    for (int nt = 0; nt < 8; nt++) {
        int col = nt * 8 + 2 * tig;
        *(__half2*)&out[ro0 + col] =
            __floats2half2_rn(oacc[nt][0] * inv0, oacc[nt][1] * inv0);
        *(__half2*)&out[ro1 + col] =
            __floats2half2_rn(oacc[nt][2] * inv1, oacc[nt][3] * inv1);
    }
}

// ---------------------------------------------------------------------------
// Launch
// ---------------------------------------------------------------------------
static constexpr int GEMM_SMEM = 3 * 32768;  // 98304 bytes

extern "C" void kernel_launch(void* const* d_in, const int* in_sizes, int n_in,
                              void* d_out, int out_size)
{
    const float* x           = (const float*)d_in[0];
    const float* ln1_g       = (const float*)d_in[1];
    const float* ln1_b       = (const float*)d_in[2];
    const float* attn_w      = (const float*)d_in[3];
    const float* attn_b      = (const float*)d_in[4];
    const float* attn_proj_w = (const float*)d_in[5];
    const float* attn_proj_b = (const float*)d_in[6];
    const float* ln2_g       = (const float*)d_in[7];
    const float* ln2_b       = (const float*)d_in[8];
    const float* fc_w        = (const float*)d_in[9];
    const float* fc_b        = (const float*)d_in[10];
    const float* mlp_proj_w  = (const float*)d_in[11];
    const float* mlp_proj_b  = (const float*)d_in[12];
    float* out = (float*)d_out;

    __half *h, *kqvb, *att, *mid, *wT1, *wT2, *wT3, *wT4;
    float *x1;
    cudaGetSymbolAddress((void**)&h,    g_h);
    cudaGetSymbolAddress((void**)&kqvb, g_kqv);
    cudaGetSymbolAddress((void**)&att,  g_att);
    cudaGetSymbolAddress((void**)&x1,   g_x1);
    cudaGetSymbolAddress((void**)&mid,  g_mid);
    cudaGetSymbolAddress((void**)&wT1,  g_wT1);
    cudaGetSymbolAddress((void**)&wT2,  g_wT2);
    cudaGetSymbolAddress((void**)&wT3,  g_wT3);
    cudaGetSymbolAddress((void**)&wT4,  g_wT4);

    static bool attr_set = false;
    if (!attr_set) {
        cudaFuncSetAttribute((const void*)gemm_h<0, __half>, cudaFuncAttributeMaxDynamicSharedMemorySize, GEMM_SMEM);
        cudaFuncSetAttribute((const void*)gemm_h<1, __half>, cudaFuncAttributeMaxDynamicSharedMemorySize, GEMM_SMEM);
        cudaFuncSetAttribute((const void*)gemm_h<2, float>,  cudaFuncAttributeMaxDynamicSharedMemorySize, GEMM_SMEM);
        cudaFuncSetAttribute((const void*)attn_h, cudaFuncAttributeMaxDynamicSharedMemorySize, ATT_SMEM);
        attr_set = true;
    }

    // weight transposes: [K,N] fp32 -> [N,K] half
    transpose_kernel<<<dim3(C3 / 32, Cc / 32), dim3(32, 8)>>>(attn_w,      wT1, Cc, C3);
    transpose_kernel<<<dim3(Cc / 32, Cc / 32), dim3(32, 8)>>>(attn_proj_w, wT2, Cc, Cc);
    transpose_kernel<<<dim3(FF / 32, Cc / 32), dim3(32, 8)>>>(fc_w,        wT3, Cc, FF);
    transpose_kernel<<<dim3(Cc / 32, FF / 32), dim3(32, 8)>>>(mlp_proj_w,  wT4, FF, Cc);

    // 1. h = LN1(x)
    ln_kernel<<<BT, 256>>>(x, ln1_g, ln1_b, h);
    // 2. kqv = h @ attn_w + attn_b   (half out — feeds attention)
    gemm_h<0, __half><<<dim3(C3 / 128, BT / 128), 256, GEMM_SMEM>>>(h, wT1, attn_b, nullptr, kqvb, BT, C3, Cc);
    // 3. causal attention (fp16 tensor cores)
    attn_h<<<dim3(Tt / 64, Bb * Hh), 128, ATT_SMEM>>>(kqvb, att);
    // 4. x1 = x + att @ attn_proj_w + attn_proj_b
    gemm_h<2, float><<<dim3(Cc / 128, BT / 128), 256, GEMM_SMEM>>>(att, wT2, attn_proj_b, x, x1, BT, Cc, Cc);
    // 5. h = LN2(x1)
    ln_kernel<<<BT, 256>>>(x1, ln2_g, ln2_b, h);
    // 6. mid = gelu(h @ fc_w + fc_b)  (half out)
    gemm_h<1, __half><<<dim3(FF / 128, BT / 128), 256, GEMM_SMEM>>>(h, wT3, fc_b, nullptr, mid, BT, FF, Cc);
    // 7. out = x1 + mid @ mlp_proj_w + mlp_proj_b
    gemm_h<2, float><<<dim3(Cc / 128, BT / 128), 256, GEMM_SMEM>>>(mid, wT4, mlp_proj_b, x1, out, BT, Cc, FF);
}